// round 13
// baseline (speedup 1.0000x reference)
#include <cuda_runtime.h>
#include <cuda.h>
#include <cuda_fp16.h>
#include <cstdint>

// ---------------------------------------------------------------------------
// MixtureLinear: out[b,n,o] = sum_{c,r} x[b,n,c]*coef[n,r]*weight[o,c,r]
//                           + sum_r coef[n,r]*bias[o,r]
// R13 = R9 mainloop (register-synthesized A via PRMT+HMUL2, TK=128, 4 stages,
//       tail split-K + separate reduce) at CTA 128x64 / warp tile 32x32 with
//       __launch_bounds__(288,2): 2 CTAs per SM so chunk-boundary and LDSM
//       latency in one CTA is hidden by the other's MMAs.
// ---------------------------------------------------------------------------

#define B_ 8
#define N_ 1024
#define C_ 768
#define O_ 768
#define R_ 16
#define M_ (B_*N_)     // 8192
#define K_ (C_*R_)     // 12288

#define TM 128
#define TN 64
#define TK 128         // y-cols per chunk = 8 c-values; 2 B sub-tiles
#define STAGES 4
#define NCHUNK_FULL 96 // K_/TK
#define NCHUNK_QTR  24
#define NTILES 12      // O_/TN
#define FULL_TILES 592 // = 2 waves * 296 slots (2 CTA/SM * 148)
#define SPLIT_TILES 176 // 768-592
#define GRID_GEMM (FULL_TILES + SPLIT_TILES*4)   // 1296

// SMEM layout: per stage [B0 8KB | B1 8KB | X 4KB]
#define SM_FULL(s)  ((unsigned)(s)*8u)
#define SM_EMPTY(s) (32u + (unsigned)(s)*8u)
#define SM_TILE   1024u
#define SUB_BYTES   8192u
#define X_OFF       16384u
#define STAGE_BYTES 20480u
#define SMEM_TOTAL (SM_TILE + STAGES*STAGE_BYTES)  // 82944

// Scratch (device globals: no allocations allowed)
__device__ __align__(1024) __half g_x16[(size_t)M_ * C_];           // 12.6 MB
__device__ __align__(1024) __half g_w2 [(size_t)O_ * K_];           // 18.9 MB
__device__ __align__(1024) float  g_bt [(size_t)N_ * O_];           // 3 MB
__device__ __align__(1024) float  g_part[(size_t)SPLIT_TILES*4*TM*TN]; // 23 MB

// ---------------------------------------------------------------------------
// PTX helpers (baseline-target only; tcgen05 is rejected by compute_103)
// ---------------------------------------------------------------------------
__device__ __forceinline__ uint32_t smem_u32(const void* p) {
    uint32_t a;
    asm("{ .reg .u64 t; cvta.to.shared.u64 t, %1; cvt.u32.u64 %0, t; }"
        : "=r"(a) : "l"(p));
    return a;
}

#define MBAR_INIT(addr, cnt) \
    asm volatile("mbarrier.init.shared.b64 [%0], %1;" :: "r"(addr), "r"(cnt) : "memory")

#define MBAR_EXPECT_TX(addr, bytes) \
    asm volatile("mbarrier.arrive.expect_tx.shared.b64 _, [%0], %1;" \
                 :: "r"(addr), "r"(bytes) : "memory")

#define MBAR_ARRIVE(addr) \
    asm volatile("mbarrier.arrive.release.cta.shared::cta.b64 _, [%0];" \
                 :: "r"(addr) : "memory")

__device__ __forceinline__ void mbar_wait(uint32_t addr, uint32_t parity) {
    asm volatile(
        "{\n\t.reg .pred P;\n\t"
        "W_%=:\n\t"
        "mbarrier.try_wait.parity.acquire.cta.shared::cta.b64 P, [%0], %1, 0x989680;\n\t"
        "@P bra.uni D_%=;\n\t"
        "bra.uni W_%=;\n\t"
        "D_%=:\n\t}"
        :: "r"(addr), "r"(parity) : "memory");
}

__device__ __forceinline__ void tma_2d(uint32_t smem_dst, const void* map,
                                       int cx, int cy, uint32_t mbar) {
    asm volatile(
        "cp.async.bulk.tensor.2d.shared::cta.global.tile.mbarrier::complete_tx::bytes "
        "[%0], [%1, {%2, %3}], [%4];"
        :: "r"(smem_dst), "l"(map), "r"(cx), "r"(cy), "r"(mbar) : "memory");
}

__device__ __forceinline__ void ldsm4(uint32_t* r, uint32_t addr) {
    asm volatile("ldmatrix.sync.aligned.m8n8.x4.shared.b16 {%0,%1,%2,%3}, [%4];"
                 : "=r"(r[0]), "=r"(r[1]), "=r"(r[2]), "=r"(r[3]) : "r"(addr));
}

__device__ __forceinline__ void lds128(uint32_t* r, uint32_t addr) {
    asm volatile("ld.shared.v4.b32 {%0,%1,%2,%3}, [%4];"
                 : "=r"(r[0]), "=r"(r[1]), "=r"(r[2]), "=r"(r[3]) : "r"(addr));
}

__device__ __forceinline__ uint32_t prmt(uint32_t s, uint32_t sel) {
    uint32_t d;
    asm("prmt.b32 %0, %1, %1, %2;" : "=r"(d) : "r"(s), "r"(sel));
    return d;
}

__device__ __forceinline__ uint32_t hm2(uint32_t a, uint32_t b) {
    uint32_t d;
    asm("mul.rn.f16x2 %0, %1, %2;" : "=r"(d) : "r"(a), "r"(b));
    return d;
}

__device__ __forceinline__ void mma16816(float* c, const uint32_t* a, const uint32_t* b) {
    asm volatile(
        "mma.sync.aligned.m16n8k16.row.col.f32.f16.f16.f32 "
        "{%0,%1,%2,%3}, {%4,%5,%6,%7}, {%8,%9}, {%0,%1,%2,%3};"
        : "+f"(c[0]), "+f"(c[1]), "+f"(c[2]), "+f"(c[3])
        : "r"(a[0]), "r"(a[1]), "r"(a[2]), "r"(a[3]), "r"(b[0]), "r"(b[1]));
}

// ---------------------------------------------------------------------------
// Fused prep kernel: x fp32->fp16 / w fp32->fp16 / bias table (R9 exact)
// ---------------------------------------------------------------------------
#define PREP_X_BLKS  ((M_*(size_t)C_/8)/256)          // 3072
#define PREP_W_BLKS  ((O_*(size_t)K_/8)/256)          // 4608
#define PREP_BT_BLKS ((N_*(size_t)O_)/256)            // 3072

__global__ void prep_all_kernel(const float* __restrict__ x,
                                const float* __restrict__ coef,
                                const float* __restrict__ w,
                                const float* __restrict__ bias,
                                __half* __restrict__ x16,
                                __half* __restrict__ w2,
                                float* __restrict__ bt) {
    size_t blk = blockIdx.x;
    if (blk < PREP_X_BLKS) {
        size_t i = blk * 256 + threadIdx.x;   // 8-float groups over M_*C_
        const float4* src = (const float4*)x + 2*i;
        float4 v0 = src[0], v1 = src[1];
        __half2 h[4];
        h[0] = __floats2half2_rn(v0.x, v0.y);
        h[1] = __floats2half2_rn(v0.z, v0.w);
        h[2] = __floats2half2_rn(v1.x, v1.y);
        h[3] = __floats2half2_rn(v1.z, v1.w);
        ((uint4*)x16)[i] = *(const uint4*)h;
    } else if (blk < PREP_X_BLKS + PREP_W_BLKS) {
        size_t i = (blk - PREP_X_BLKS) * 256 + threadIdx.x;  // 8-float groups
        const float4* src = (const float4*)w + 2*i;
        float4 v0 = src[0], v1 = src[1];
        __half2 h[4];
        h[0] = __floats2half2_rn(v0.x, v0.y);
        h[1] = __floats2half2_rn(v0.z, v0.w);
        h[2] = __floats2half2_rn(v1.x, v1.y);
        h[3] = __floats2half2_rn(v1.z, v1.w);
        ((uint4*)w2)[i] = *(const uint4*)h;
    } else {
        size_t i = (blk - PREP_X_BLKS - PREP_W_BLKS) * 256 + threadIdx.x; // N_*O_
        int o = (int)(i % O_), n = (int)(i / O_);
        const float4* cf = (const float4*)(coef + (size_t)n * R_);
        const float4* bf = (const float4*)(bias + (size_t)o * R_);
        float s = 0.f;
#pragma unroll
        for (int q = 0; q < 4; q++) {
            float4 a = cf[q], b = bf[q];
            s += a.x*b.x + a.y*b.y + a.z*b.z + a.w*b.w;
        }
        bt[i] = s;
    }
}

// ---------------------------------------------------------------------------
// Reduce kernel: sum 4 split-K partials + bias into out (split tiles only).
// Fixed summation order -> bitwise deterministic.
// ---------------------------------------------------------------------------
#define REDUCE_ELEMS ((size_t)SPLIT_TILES * TM * TN)   // 1,441,792
__global__ void reduce_kernel(const float* __restrict__ part,
                              const float* __restrict__ bt,
                              float* __restrict__ out) {
    size_t idx = (size_t)blockIdx.x * 256 + threadIdx.x;
    int t = (int)(idx >> 13);          // split-tile index 0..175 (8192 elems)
    int e = (int)(idx & 8191);         // element within 128x64 tile
    int tile = FULL_TILES + t;
    int mt = tile / NTILES, nt = tile % NTILES;
    int row = e >> 6, col = e & 63;
    int m = mt * TM + row;
    int o = nt * TN + col;
    const float* p = part + ((size_t)t * 4) * (TM*TN) + e;
    float v = ((p[0] + p[TM*TN]) + (p[2*TM*TN] + p[3*TM*TN]))
            + bt[(size_t)(m & (N_-1)) * O_ + o];
    out[(size_t)m * O_ + o] = v;
}

// ---------------------------------------------------------------------------
// GEMM kernel. CTA 128x64, 2 CTAs/SM. 8 compute warps (4m x 2n, warp 32x32)
// + 1 TMA producer warp. A synthesized from x-tile (smem) * coef (registers).
// bid < 592: full-K tile -> out (+bias); bid >= 592: quarter unit -> g_part.
// ---------------------------------------------------------------------------
__global__ void __launch_bounds__(288, 2) gemm_kernel(
    const __grid_constant__ CUtensorMap tma_b,
    const __grid_constant__ CUtensorMap tma_x,
    const float* __restrict__ coef,
    const float* __restrict__ bt,
    float* __restrict__ part,
    float* __restrict__ out)
{
    extern __shared__ __align__(1024) char smem[];
    uint32_t sb = smem_u32(smem);
    int tid  = threadIdx.x;
    int lane = tid & 31;
    int wid  = tid >> 5;

    int bid = blockIdx.x;
    bool isfull = bid < FULL_TILES;
    int tile, kq;
    if (isfull) { tile = bid; kq = 0; }
    else        { int u = bid - FULL_TILES; tile = FULL_TILES + (u >> 2); kq = u & 3; }
    int ntile = tile % NTILES;
    int mtile = tile / NTILES;
    int nchunk = isfull ? NCHUNK_FULL : NCHUNK_QTR;
    int k0 = kq * NCHUNK_QTR;          // chunk offset

    if (tid == 0) {
        for (int s = 0; s < STAGES; s++) {
            MBAR_INIT(sb + SM_FULL(s), 1);
            MBAR_INIT(sb + SM_EMPTY(s), 8);
        }
    }
    __syncthreads();

    if (wid == 8) {
        // ------------------- producer warp (TMA) -------------------
        if (lane == 0) {
            int s = 0, pe = 0;
            for (int i = 0; i < nchunk; i++) {
                uint32_t st = sb + SM_TILE + (uint32_t)s * STAGE_BYTES;
                if (i >= STAGES) mbar_wait(sb + SM_EMPTY(s), (uint32_t)pe);
                MBAR_EXPECT_TX(sb + SM_FULL(s), STAGE_BYTES);
                int cx  = (k0 + i) * TK;       // B k-coord (halfs)
                int cxx = (k0 + i) * 8;        // x c-coord (halfs); box 16, OOB=0
                tma_2d(st,             &tma_b, cx,      ntile * TN, sb + SM_FULL(s));
                tma_2d(st + SUB_BYTES, &tma_b, cx + 64, ntile * TN, sb + SM_FULL(s));
                tma_2d(st + X_OFF,     &tma_x, cxx,     mtile * TM, sb + SM_FULL(s));
                if (++s == STAGES) { s = 0; if (i >= STAGES) pe ^= 1; }
            }
        }
        return;
    }

    // ------------------- compute warps -------------------
    int wr = wid & 3;   // warp row (m): 0..3
    int wc = wid >> 2;  // warp col (n): 0..1

    // B fragment smem addressing (SW128 swizzle: col ^= (row&7)<<4)
    int g = lane >> 3;
    int rowB0  = wc * 32 + ((g & 2) << 2) + (lane & 7);
    uint32_t offB0 = (uint32_t)rowB0 * 128;   // +p*16*128 per ldsm pair p
    uint32_t swB   = (uint32_t)(rowB0 & 7) << 4;
    uint32_t bcolg = (uint32_t)(g & 1) << 4;

    // A synthesis setup: rows l/4 + {0,8,16,24}, r-pairs (2j,2j+1),(2j+8,2j+9)
    int j2 = (lane & 3) * 2;
    int rloc0 = wr * 32 + (lane >> 2);
    uint32_t ch[4][2];
    uint32_t xvoff[4];
#pragma unroll
    for (int q = 0; q < 4; q++) {
        int rl = rloc0 + 8 * q;
        int n = (mtile * TM + rl) & (N_ - 1);
        float2 p0 = *(const float2*)(coef + (size_t)n * R_ + j2);
        float2 p1 = *(const float2*)(coef + (size_t)n * R_ + j2 + 8);
        __half2 h0 = __floats2half2_rn(p0.x, p0.y);
        __half2 h1 = __floats2half2_rn(p1.x, p1.y);
        ch[q][0] = *(uint32_t*)&h0;
        ch[q][1] = *(uint32_t*)&h1;
        xvoff[q] = X_OFF + (uint32_t)rl * 32u;   // x slot row stride = 32B
    }

    float acc[2][4][4];
#pragma unroll
    for (int mi = 0; mi < 2; mi++)
#pragma unroll
        for (int nb = 0; nb < 4; nb++)
#pragma unroll
            for (int q = 0; q < 4; q++) acc[mi][nb][q] = 0.f;

    uint32_t xv[4][4];      // per-chunk x values: 4 rows x 8 halfs
    uint32_t fa[2][8];      // [buf][mi*4+reg] synthesized A frags
    uint32_t fb[2][2][4];   // [buf][p][4] B frags

#define LD_XV(stg) do {                                                        \
        lds128(xv[0], (stg) + xvoff[0]);                                       \
        lds128(xv[1], (stg) + xvoff[1]);                                       \
        lds128(xv[2], (stg) + xvoff[2]);                                       \
        lds128(xv[3], (stg) + xvoff[3]);                                       \
    } while (0)

#define LD_B(buf, stg, t) do {                                                 \
        uint32_t bB_ = (stg) + (uint32_t)((t) >> 2) * SUB_BYTES;               \
        uint32_t kb_ = (uint32_t)((t) & 3) * 32u;                              \
        ldsm4(fb[buf][0], bB_ + offB0 +    0u + ((kb_ + bcolg) ^ swB));        \
        ldsm4(fb[buf][1], bB_ + offB0 + 2048u + ((kb_ + bcolg) ^ swB));        \
    } while (0)

#define SYNTH(buf, t) do {                                                     \
        uint32_t sel_ = ((t) & 1) ? 0x3232u : 0x1010u;                         \
        uint32_t s0_ = prmt(xv[0][(t) >> 1], sel_);                            \
        uint32_t s1_ = prmt(xv[1][(t) >> 1], sel_);                            \
        uint32_t s2_ = prmt(xv[2][(t) >> 1], sel_);                            \
        uint32_t s3_ = prmt(xv[3][(t) >> 1], sel_);                            \
        fa[buf][0] = hm2(s0_, ch[0][0]);                                       \
        fa[buf][1] = hm2(s1_, ch[1][0]);                                       \
        fa[buf][2] = hm2(s0_, ch[0][1]);                                       \
        fa[buf][3] = hm2(s1_, ch[1][1]);                                       \
        fa[buf][4] = hm2(s2_, ch[2][0]);                                       \
        fa[buf][5] = hm2(s3_, ch[3][0]);                                       \
        fa[buf][6] = hm2(s2_, ch[2][1]);                                       \
        fa[buf][7] = hm2(s3_, ch[3][1]);                                       \
    } while (0)

#define DO_MMAS(buf) do {                                                      \
        _Pragma("unroll")                                                      \
        for (int nb = 0; nb < 4; nb++) {                                       \
            const uint32_t* bp = &fb[buf][nb >> 1][(nb & 1) * 2];              \
            mma16816(acc[0][nb], &fa[buf][0], bp);                             \
            mma16816(acc[1][nb], &fa[buf][4], bp);                             \
        }                                                                      \
    } while (0)

    // Preload chunk 0, step 0
    {
        uint32_t stg0 = sb + SM_TILE;
        mbar_wait(sb + SM_FULL(0), 0);
        LD_XV(stg0);
        LD_B(0, stg0, 0);
        SYNTH(0, 0);
    }

    int sc = 0, pc = 0;
    for (int i = 0; i < nchunk; i++) {
        uint32_t stg = sb + SM_TILE + (uint32_t)sc * STAGE_BYTES;
        // steps 0..6: prefetch B + synthesize A for step t+1, MMA step t
#pragma unroll
        for (int t = 0; t < 7; t++) {
            LD_B((t + 1) & 1, stg, t + 1);
            SYNTH((t + 1) & 1, t + 1);
            DO_MMAS(t & 1);
        }
        // step 7: stage fully read -> arrive empty; load next chunk x/B/A0
        if (lane == 0) MBAR_ARRIVE(sb + SM_EMPTY(sc));
        if (++sc == STAGES) { sc = 0; pc ^= 1; }
        if (i + 1 < nchunk) {
            uint32_t stg2 = sb + SM_TILE + (uint32_t)sc * STAGE_BYTES;
            mbar_wait(sb + SM_FULL(sc), (uint32_t)pc);
            LD_XV(stg2);
            LD_B(0, stg2, 0);
            SYNTH(0, 0);        // fa[0] free (last used at t=6's DO_MMAS(0))
        }
        DO_MMAS(1);
    }

    // Epilogue
    if (isfull) {
        int mBase = mtile * TM + wr * 32 + (lane >> 2);
        int col   = ntile * TN + wc * 32 + (lane & 3) * 2;
#pragma unroll
        for (int mi = 0; mi < 2; mi++) {
#pragma unroll
            for (int nb = 0; nb < 4; nb++) {
                int c0 = col + nb * 8;
                int m0 = mBase + mi * 16;
                int m1 = m0 + 8;
                const float2 b0 = *(const float2*)(bt + (size_t)(m0 & (N_-1)) * O_ + c0);
                const float2 b1 = *(const float2*)(bt + (size_t)(m1 & (N_-1)) * O_ + c0);
                float2 v0, v1;
                v0.x = acc[mi][nb][0] + b0.x;  v0.y = acc[mi][nb][1] + b0.y;
                v1.x = acc[mi][nb][2] + b1.x;  v1.y = acc[mi][nb][3] + b1.y;
                *(float2*)(out + (size_t)m0 * O_ + c0) = v0;
                *(float2*)(out + (size_t)m1 * O_ + c0) = v1;
            }
        }
    } else {
        float* pp = part + ((size_t)(tile - FULL_TILES) * 4 + kq) * (TM*TN);
        int rloc = wr * 32 + (lane >> 2);
        int cloc = wc * 32 + (lane & 3) * 2;
#pragma unroll
        for (int mi = 0; mi < 2; mi++) {
#pragma unroll
            for (int nb = 0; nb < 4; nb++) {
                int c0 = cloc + nb * 8;
                int r0 = rloc + mi * 16;
                float2 v0, v1;
                v0.x = acc[mi][nb][0];  v0.y = acc[mi][nb][1];
                v1.x = acc[mi][nb][2];  v1.y = acc[mi][nb][3];
                *(float2*)(pp + (size_t)r0 * TN + c0)       = v0;
                *(float2*)(pp + (size_t)(r0 + 8) * TN + c0) = v1;
            }
        }
    }
}

// ---------------------------------------------------------------------------
// Host launch
// ---------------------------------------------------------------------------
typedef CUresult (*EncodeFn)(
    CUtensorMap*, CUtensorMapDataType, cuuint32_t, void*,
    const cuuint64_t*, const cuuint64_t*, const cuuint32_t*, const cuuint32_t*,
    CUtensorMapInterleave, CUtensorMapSwizzle, CUtensorMapL2promotion,
    CUtensorMapFloatOOBfill);

extern "C" void kernel_launch(void* const* d_in, const int* in_sizes, int n_in,
                              void* d_out, int out_size) {
    const float* x    = (const float*)d_in[0];
    const float* coef = (const float*)d_in[1];
    const float* w    = (const float*)d_in[2];
    const float* bias = (const float*)d_in[3];
    float* out = (float*)d_out;

    void *px16 = nullptr, *pw2 = nullptr, *pbt = nullptr, *ppart = nullptr;
    cudaGetSymbolAddress(&px16, g_x16);
    cudaGetSymbolAddress(&pw2, g_w2);
    cudaGetSymbolAddress(&pbt, g_bt);
    cudaGetSymbolAddress(&ppart, g_part);

    prep_all_kernel<<<(unsigned)(PREP_X_BLKS + PREP_W_BLKS + PREP_BT_BLKS), 256>>>(
        x, coef, w, bias, (__half*)px16, (__half*)pw2, (float*)pbt);

    EncodeFn encode = nullptr;
    cudaDriverEntryPointQueryResult qr;
    cudaGetDriverEntryPoint("cuTensorMapEncodeTiled", (void**)&encode,
                            cudaEnableDefault, &qr);

    CUtensorMap tb{}, tx{};
    {   // B: w2 (O, K) fp16, K-major, SW128, box {64, TN}
        cuuint64_t dims[2]    = {(cuuint64_t)K_, (cuuint64_t)O_};
        cuuint64_t strides[1] = {(cuuint64_t)K_ * 2};
        cuuint32_t box[2]     = {64, TN};
        cuuint32_t es[2]      = {1, 1};
        encode(&tb, CU_TENSOR_MAP_DATA_TYPE_FLOAT16, 2, pw2, dims, strides, box, es,
               CU_TENSOR_MAP_INTERLEAVE_NONE, CU_TENSOR_MAP_SWIZZLE_128B,
               CU_TENSOR_MAP_L2_PROMOTION_L2_128B, CU_TENSOR_MAP_FLOAT_OOB_FILL_NONE);
    }
    {   // X: x16 (M, C) fp16, box {16, TM} (32B rows = TMA minimum), no swizzle
        cuuint64_t dims[2]    = {(cuuint64_t)C_, (cuuint64_t)M_};
        cuuint64_t strides[1] = {(cuuint64_t)C_ * 2};
        cuuint32_t box[2]     = {16, TM};
        cuuint32_t es[2]      = {1, 1};
        encode(&tx, CU_TENSOR_MAP_DATA_TYPE_FLOAT16, 2, px16, dims, strides, box, es,
               CU_TENSOR_MAP_INTERLEAVE_NONE, CU_TENSOR_MAP_SWIZZLE_NONE,
               CU_TENSOR_MAP_L2_PROMOTION_L2_128B, CU_TENSOR_MAP_FLOAT_OOB_FILL_NONE);
    }

    cudaFuncSetAttribute(gemm_kernel, cudaFuncAttributeMaxDynamicSharedMemorySize,
                         SMEM_TOTAL);
    gemm_kernel<<<GRID_GEMM, 288, SMEM_TOTAL>>>(tb, tx, coef, (const float*)pbt,
                                                (float*)ppart, out);

    reduce_kernel<<<(unsigned)(REDUCE_ELEMS / 256), 256>>>(
        (const float*)ppart, (const float*)pbt, out);
}

// round 14
// speedup vs baseline: 1.0767x; 1.0767x over previous
#include <cuda_runtime.h>
#include <cuda.h>
#include <cuda_fp16.h>
#include <cstdint>

// ---------------------------------------------------------------------------
// MixtureLinear: out[b,n,o] = sum_{c,r} x[b,n,c]*coef[n,r]*weight[o,c,r]
//                           + sum_r coef[n,r]*bias[o,r]
// R14 = R9 (register-synthesized A, TK=128, 4 stages, CTA 128x128,
//       warp tile 32x64, 1 CTA/SM) with:
//       (a) 8-way tail split-K (88 tiles -> 704 twelfth-chunk units) for a
//           tighter tail wave (2.75tau -> 2.625tau), reduce sums 8 partials;
//       (b) chunk-boundary DO_MMAS issued BEFORE the next-stage mbar wait so
//           the TRYWAIT latency overlaps tensor work.
// ---------------------------------------------------------------------------

#define B_ 8
#define N_ 1024
#define C_ 768
#define O_ 768
#define R_ 16
#define M_ (B_*N_)     // 8192
#define K_ (C_*R_)     // 12288

#define TM 128
#define TN 128
#define TK 128         // y-cols per chunk = 8 c-values; 2 B sub-tiles
#define STAGES 4
#define NCHUNK_FULL 96 // K_/TK
#define NCHUNK_8TH  12
#define NTILES 6       // O_/TN
#define FULL_TILES 296 // = 2*148 exact waves
#define SPLIT_TILES 88 // 384-296
#define GRID_GEMM (FULL_TILES + SPLIT_TILES*8)   // 1000

// SMEM layout: per stage [B0 16KB | B1 16KB | X 4KB]
#define SM_FULL(s)  ((unsigned)(s)*8u)
#define SM_EMPTY(s) (32u + (unsigned)(s)*8u)
#define SM_TILE   1024u
#define SUB_BYTES   16384u
#define X_OFF       32768u
#define STAGE_BYTES 36864u
#define SMEM_TOTAL (SM_TILE + STAGES*STAGE_BYTES)  // 148480

// Scratch (device globals: no allocations allowed)
__device__ __align__(1024) __half g_x16[(size_t)M_ * C_];           // 12.6 MB
__device__ __align__(1024) __half g_w2 [(size_t)O_ * K_];           // 18.9 MB
__device__ __align__(1024) float  g_bt [(size_t)N_ * O_];           // 3 MB
__device__ __align__(1024) float  g_part[(size_t)SPLIT_TILES*8*TM*TN]; // 46 MB

// ---------------------------------------------------------------------------
// PTX helpers (baseline-target only; tcgen05 is rejected by compute_103)
// ---------------------------------------------------------------------------
__device__ __forceinline__ uint32_t smem_u32(const void* p) {
    uint32_t a;
    asm("{ .reg .u64 t; cvta.to.shared.u64 t, %1; cvt.u32.u64 %0, t; }"
        : "=r"(a) : "l"(p));
    return a;
}

#define MBAR_INIT(addr, cnt) \
    asm volatile("mbarrier.init.shared.b64 [%0], %1;" :: "r"(addr), "r"(cnt) : "memory")

#define MBAR_EXPECT_TX(addr, bytes) \
    asm volatile("mbarrier.arrive.expect_tx.shared.b64 _, [%0], %1;" \
                 :: "r"(addr), "r"(bytes) : "memory")

#define MBAR_ARRIVE(addr) \
    asm volatile("mbarrier.arrive.release.cta.shared::cta.b64 _, [%0];" \
                 :: "r"(addr) : "memory")

__device__ __forceinline__ void mbar_wait(uint32_t addr, uint32_t parity) {
    asm volatile(
        "{\n\t.reg .pred P;\n\t"
        "W_%=:\n\t"
        "mbarrier.try_wait.parity.acquire.cta.shared::cta.b64 P, [%0], %1, 0x989680;\n\t"
        "@P bra.uni D_%=;\n\t"
        "bra.uni W_%=;\n\t"
        "D_%=:\n\t}"
        :: "r"(addr), "r"(parity) : "memory");
}

__device__ __forceinline__ void tma_2d(uint32_t smem_dst, const void* map,
                                       int cx, int cy, uint32_t mbar) {
    asm volatile(
        "cp.async.bulk.tensor.2d.shared::cta.global.tile.mbarrier::complete_tx::bytes "
        "[%0], [%1, {%2, %3}], [%4];"
        :: "r"(smem_dst), "l"(map), "r"(cx), "r"(cy), "r"(mbar) : "memory");
}

__device__ __forceinline__ void ldsm4(uint32_t* r, uint32_t addr) {
    asm volatile("ldmatrix.sync.aligned.m8n8.x4.shared.b16 {%0,%1,%2,%3}, [%4];"
                 : "=r"(r[0]), "=r"(r[1]), "=r"(r[2]), "=r"(r[3]) : "r"(addr));
}

__device__ __forceinline__ void lds128(uint32_t* r, uint32_t addr) {
    asm volatile("ld.shared.v4.b32 {%0,%1,%2,%3}, [%4];"
                 : "=r"(r[0]), "=r"(r[1]), "=r"(r[2]), "=r"(r[3]) : "r"(addr));
}

__device__ __forceinline__ uint32_t prmt(uint32_t s, uint32_t sel) {
    uint32_t d;
    asm("prmt.b32 %0, %1, %1, %2;" : "=r"(d) : "r"(s), "r"(sel));
    return d;
}

__device__ __forceinline__ uint32_t hm2(uint32_t a, uint32_t b) {
    uint32_t d;
    asm("mul.rn.f16x2 %0, %1, %2;" : "=r"(d) : "r"(a), "r"(b));
    return d;
}

__device__ __forceinline__ void mma16816(float* c, const uint32_t* a, const uint32_t* b) {
    asm volatile(
        "mma.sync.aligned.m16n8k16.row.col.f32.f16.f16.f32 "
        "{%0,%1,%2,%3}, {%4,%5,%6,%7}, {%8,%9}, {%0,%1,%2,%3};"
        : "+f"(c[0]), "+f"(c[1]), "+f"(c[2]), "+f"(c[3])
        : "r"(a[0]), "r"(a[1]), "r"(a[2]), "r"(a[3]), "r"(b[0]), "r"(b[1]));
}

// ---------------------------------------------------------------------------
// Fused prep kernel: x fp32->fp16 / w fp32->fp16 / bias table (R9 exact)
// ---------------------------------------------------------------------------
#define PREP_X_BLKS  ((M_*(size_t)C_/8)/256)          // 3072
#define PREP_W_BLKS  ((O_*(size_t)K_/8)/256)          // 4608
#define PREP_BT_BLKS ((N_*(size_t)O_)/256)            // 3072

__global__ void prep_all_kernel(const float* __restrict__ x,
                                const float* __restrict__ coef,
                                const float* __restrict__ w,
                                const float* __restrict__ bias,
                                __half* __restrict__ x16,
                                __half* __restrict__ w2,
                                float* __restrict__ bt) {
    size_t blk = blockIdx.x;
    if (blk < PREP_X_BLKS) {
        size_t i = blk * 256 + threadIdx.x;   // 8-float groups over M_*C_
        const float4* src = (const float4*)x + 2*i;
        float4 v0 = src[0], v1 = src[1];
        __half2 h[4];
        h[0] = __floats2half2_rn(v0.x, v0.y);
        h[1] = __floats2half2_rn(v0.z, v0.w);
        h[2] = __floats2half2_rn(v1.x, v1.y);
        h[3] = __floats2half2_rn(v1.z, v1.w);
        ((uint4*)x16)[i] = *(const uint4*)h;
    } else if (blk < PREP_X_BLKS + PREP_W_BLKS) {
        size_t i = (blk - PREP_X_BLKS) * 256 + threadIdx.x;  // 8-float groups
        const float4* src = (const float4*)w + 2*i;
        float4 v0 = src[0], v1 = src[1];
        __half2 h[4];
        h[0] = __floats2half2_rn(v0.x, v0.y);
        h[1] = __floats2half2_rn(v0.z, v0.w);
        h[2] = __floats2half2_rn(v1.x, v1.y);
        h[3] = __floats2half2_rn(v1.z, v1.w);
        ((uint4*)w2)[i] = *(const uint4*)h;
    } else {
        size_t i = (blk - PREP_X_BLKS - PREP_W_BLKS) * 256 + threadIdx.x; // N_*O_
        int o = (int)(i % O_), n = (int)(i / O_);
        const float4* cf = (const float4*)(coef + (size_t)n * R_);
        const float4* bf = (const float4*)(bias + (size_t)o * R_);
        float s = 0.f;
#pragma unroll
        for (int q = 0; q < 4; q++) {
            float4 a = cf[q], b = bf[q];
            s += a.x*b.x + a.y*b.y + a.z*b.z + a.w*b.w;
        }
        bt[i] = s;
    }
}

// ---------------------------------------------------------------------------
// Reduce kernel: sum 8 split-K partials + bias into out (split tiles only).
// Fixed summation order -> bitwise deterministic.
// ---------------------------------------------------------------------------
#define REDUCE_ELEMS ((size_t)SPLIT_TILES * TM * TN)   // 1,441,792
__global__ void reduce_kernel(const float* __restrict__ part,
                              const float* __restrict__ bt,
                              float* __restrict__ out) {
    size_t idx = (size_t)blockIdx.x * 256 + threadIdx.x;
    int t = (int)(idx >> 14);          // split-tile index 0..87
    int e = (int)(idx & 16383);        // element within 128x128 tile
    int tile = FULL_TILES + t;
    int mt = tile / NTILES, nt = tile % NTILES;
    int row = e >> 7, col = e & 127;
    int m = mt * TM + row;
    int o = nt * TN + col;
    const float* p = part + ((size_t)t * 8) * (TM*TN) + e;
    const size_t S = (size_t)TM * TN;
    float v = (((p[0] + p[S]) + (p[2*S] + p[3*S]))
            +  ((p[4*S] + p[5*S]) + (p[6*S] + p[7*S])))
            + bt[(size_t)(m & (N_-1)) * O_ + o];
    out[(size_t)m * O_ + o] = v;
}

// ---------------------------------------------------------------------------
// GEMM kernel. CTA 128x128. 8 compute warps (4m x 2n, warp 32x64) + 1 TMA warp.
// A fragments synthesized from x-tile (smem) * coef (registers).
// bid < 296: full-K tile -> out (+bias); bid >= 296: eighth unit -> g_part.
// ---------------------------------------------------------------------------
__global__ void __launch_bounds__(288, 1) gemm_kernel(
    const __grid_constant__ CUtensorMap tma_b,
    const __grid_constant__ CUtensorMap tma_x,
    const float* __restrict__ coef,
    const float* __restrict__ bt,
    float* __restrict__ part,
    float* __restrict__ out)
{
    extern __shared__ __align__(1024) char smem[];
    uint32_t sb = smem_u32(smem);
    int tid  = threadIdx.x;
    int lane = tid & 31;
    int wid  = tid >> 5;

    int bid = blockIdx.x;
    bool isfull = bid < FULL_TILES;
    int tile, kq;
    if (isfull) { tile = bid; kq = 0; }
    else        { int u = bid - FULL_TILES; tile = FULL_TILES + (u >> 3); kq = u & 7; }
    int ntile = tile % NTILES;
    int mtile = tile / NTILES;
    int nchunk = isfull ? NCHUNK_FULL : NCHUNK_8TH;
    int k0 = kq * NCHUNK_8TH;          // chunk offset

    if (tid == 0) {
        for (int s = 0; s < STAGES; s++) {
            MBAR_INIT(sb + SM_FULL(s), 1);
            MBAR_INIT(sb + SM_EMPTY(s), 8);
        }
    }
    __syncthreads();

    if (wid == 8) {
        // ------------------- producer warp (TMA) -------------------
        if (lane == 0) {
            int s = 0, pe = 0;
            for (int i = 0; i < nchunk; i++) {
                uint32_t st = sb + SM_TILE + (uint32_t)s * STAGE_BYTES;
                if (i >= STAGES) mbar_wait(sb + SM_EMPTY(s), (uint32_t)pe);
                MBAR_EXPECT_TX(sb + SM_FULL(s), STAGE_BYTES);
                int cx  = (k0 + i) * TK;       // B k-coord (halfs)
                int cxx = (k0 + i) * 8;        // x c-coord (halfs); box 16, OOB=0
                tma_2d(st,             &tma_b, cx,      ntile * TN, sb + SM_FULL(s));
                tma_2d(st + SUB_BYTES, &tma_b, cx + 64, ntile * TN, sb + SM_FULL(s));
                tma_2d(st + X_OFF,     &tma_x, cxx,     mtile * TM, sb + SM_FULL(s));
                if (++s == STAGES) { s = 0; if (i >= STAGES) pe ^= 1; }
            }
        }
        return;
    }

    // ------------------- compute warps -------------------
    int wr = wid & 3;   // warp row (m): 0..3
    int wc = wid >> 2;  // warp col (n): 0..1

    // B fragment smem addressing (SW128 swizzle: col ^= (row&7)<<4)
    int g = lane >> 3;
    int rowB0  = wc * 64 + ((g & 2) << 2) + (lane & 7);
    uint32_t offB0 = (uint32_t)rowB0 * 128;   // +p*16*128 per pair p
    uint32_t swB   = (uint32_t)(rowB0 & 7) << 4;
    uint32_t bcolg = (uint32_t)(g & 1) << 4;

    // A synthesis setup: rows l/4 + {0,8,16,24}, r-pairs (2j,2j+1),(2j+8,2j+9)
    int j2 = (lane & 3) * 2;
    int rloc0 = wr * 32 + (lane >> 2);
    uint32_t ch[4][2];
    uint32_t xvoff[4];
#pragma unroll
    for (int q = 0; q < 4; q++) {
        int rl = rloc0 + 8 * q;
        int n = (mtile * TM + rl) & (N_ - 1);
        float2 p0 = *(const float2*)(coef + (size_t)n * R_ + j2);
        float2 p1 = *(const float2*)(coef + (size_t)n * R_ + j2 + 8);
        __half2 h0 = __floats2half2_rn(p0.x, p0.y);
        __half2 h1 = __floats2half2_rn(p1.x, p1.y);
        ch[q][0] = *(uint32_t*)&h0;
        ch[q][1] = *(uint32_t*)&h1;
        xvoff[q] = X_OFF + (uint32_t)rl * 32u;   // x slot row stride = 32B
    }

    float acc[2][8][4];
#pragma unroll
    for (int mi = 0; mi < 2; mi++)
#pragma unroll
        for (int nb = 0; nb < 8; nb++)
#pragma unroll
            for (int q = 0; q < 4; q++) acc[mi][nb][q] = 0.f;

    uint32_t xv[4][4];      // per-chunk x values: 4 rows x 8 halfs
    uint32_t fa[2][8];      // [buf][mi*4+reg] synthesized A frags
    uint32_t fb[2][4][4];   // [buf][p][4] B frags

#define LD_XV(stg) do {                                                        \
        lds128(xv[0], (stg) + xvoff[0]);                                       \
        lds128(xv[1], (stg) + xvoff[1]);                                       \
        lds128(xv[2], (stg) + xvoff[2]);                                       \
        lds128(xv[3], (stg) + xvoff[3]);                                       \
    } while (0)

#define LD_B(buf, stg, t) do {                                                 \
        uint32_t bB_ = (stg) + (uint32_t)((t) >> 2) * SUB_BYTES;               \
        uint32_t kb_ = (uint32_t)((t) & 3) * 32u;                              \
        ldsm4(fb[buf][0], bB_ + offB0 +    0u + ((kb_ + bcolg) ^ swB));        \
        ldsm4(fb[buf][1], bB_ + offB0 + 2048u + ((kb_ + bcolg) ^ swB));        \
        ldsm4(fb[buf][2], bB_ + offB0 + 4096u + ((kb_ + bcolg) ^ swB));        \
        ldsm4(fb[buf][3], bB_ + offB0 + 6144u + ((kb_ + bcolg) ^ swB));        \
    } while (0)

#define SYNTH(buf, t) do {                                                     \
        uint32_t sel_ = ((t) & 1) ? 0x3232u : 0x1010u;                         \
        uint32_t s0_ = prmt(xv[0][(t) >> 1], sel_);                            \
        uint32_t s1_ = prmt(xv[1][(t) >> 1], sel_);                            \
        uint32_t s2_ = prmt(xv[2][(t) >> 1], sel_);                            \
        uint32_t s3_ = prmt(xv[3][(t) >> 1], sel_);                            \
        fa[buf][0] = hm2(s0_, ch[0][0]);                                       \
        fa[buf][1] = hm2(s1_, ch[1][0]);                                       \
        fa[buf][2] = hm2(s0_, ch[0][1]);                                       \
        fa[buf][3] = hm2(s1_, ch[1][1]);                                       \
        fa[buf][4] = hm2(s2_, ch[2][0]);                                       \
        fa[buf][5] = hm2(s3_, ch[3][0]);                                       \
        fa[buf][6] = hm2(s2_, ch[2][1]);                                       \
        fa[buf][7] = hm2(s3_, ch[3][1]);                                       \
    } while (0)

#define DO_MMAS(buf) do {                                                      \
        _Pragma("unroll")                                                      \
        for (int nb = 0; nb < 8; nb++) {                                       \
            const uint32_t* bp = &fb[buf][nb >> 1][(nb & 1) * 2];              \
            mma16816(acc[0][nb], &fa[buf][0], bp);                             \
            mma16816(acc[1][nb], &fa[buf][4], bp);                             \
        }                                                                      \
    } while (0)

    // Preload chunk 0
    {
        uint32_t stg0 = sb + SM_TILE;
        mbar_wait(sb + SM_FULL(0), 0);
        LD_XV(stg0);
        LD_B(0, stg0, 0);
        SYNTH(0, 0);
    }

    int sc = 0, pc = 0;
    for (int i = 0; i < nchunk; i++) {
        uint32_t stg = sb + SM_TILE + (uint32_t)sc * STAGE_BYTES;
        // steps 0..6: prefetch B + synthesize A for step t+1, MMA step t
#pragma unroll
        for (int t = 0; t < 7; t++) {
            LD_B((t + 1) & 1, stg, t + 1);
            SYNTH((t + 1) & 1, t + 1);
            DO_MMAS(t & 1);
        }
        // stage fully read -> arrive empty; run step-7 MMAs (operands already
        // in registers) BEFORE the next-stage wait so TRYWAIT latency overlaps
        // tensor work; then load next chunk's x/B/A0.
        if (lane == 0) MBAR_ARRIVE(sb + SM_EMPTY(sc));
        DO_MMAS(1);
        if (++sc == STAGES) { sc = 0; pc ^= 1; }
        if (i + 1 < nchunk) {
            uint32_t stg2 = sb + SM_TILE + (uint32_t)sc * STAGE_BYTES;
            mbar_wait(sb + SM_FULL(sc), (uint32_t)pc);
            LD_XV(stg2);
            LD_B(0, stg2, 0);
            SYNTH(0, 0);
        }
    }

    // Epilogue
    if (isfull) {
        int mBase = mtile * TM + wr * 32 + (lane >> 2);
        int col   = ntile * TN + wc * 64 + (lane & 3) * 2;
#pragma unroll
        for (int mi = 0; mi < 2; mi++) {
#pragma unroll
            for (int nb = 0; nb < 8; nb++) {
                int c0 = col + nb * 8;
                int m0 = mBase + mi * 16;
                int m1 = m0 + 8;
                const float2 b0 = *(const float2*)(bt + (size_t)(m0 & (N_-1)) * O_ + c0);
                const float2 b1 = *(const float2*)(bt + (size_t)(m1 & (N_-1)) * O_ + c0);
                float2 v0, v1;
                v0.x = acc[mi][nb][0] + b0.x;  v0.y = acc[mi][nb][1] + b0.y;
                v1.x = acc[mi][nb][2] + b1.x;  v1.y = acc[mi][nb][3] + b1.y;
                *(float2*)(out + (size_t)m0 * O_ + c0) = v0;
                *(float2*)(out + (size_t)m1 * O_ + c0) = v1;
            }
        }
    } else {
        float* pp = part + ((size_t)(tile - FULL_TILES) * 8 + kq) * (TM*TN);
        int rloc = wr * 32 + (lane >> 2);
        int cloc = wc * 64 + (lane & 3) * 2;
#pragma unroll
        for (int mi = 0; mi < 2; mi++) {
#pragma unroll
            for (int nb = 0; nb < 8; nb++) {
                int c0 = cloc + nb * 8;
                int r0 = rloc + mi * 16;
                float2 v0, v1;
                v0.x = acc[mi][nb][0];  v0.y = acc[mi][nb][1];
                v1.x = acc[mi][nb][2];  v1.y = acc[mi][nb][3];
                *(float2*)(pp + (size_t)r0 * TN + c0)       = v0;
                *(float2*)(pp + (size_t)(r0 + 8) * TN + c0) = v1;
            }
        }
    }
}

// ---------------------------------------------------------------------------
// Host launch
// ---------------------------------------------------------------------------
typedef CUresult (*EncodeFn)(
    CUtensorMap*, CUtensorMapDataType, cuuint32_t, void*,
    const cuuint64_t*, const cuuint64_t*, const cuuint32_t*, const cuuint32_t*,
    CUtensorMapInterleave, CUtensorMapSwizzle, CUtensorMapL2promotion,
    CUtensorMapFloatOOBfill);

extern "C" void kernel_launch(void* const* d_in, const int* in_sizes, int n_in,
                              void* d_out, int out_size) {
    const float* x    = (const float*)d_in[0];
    const float* coef = (const float*)d_in[1];
    const float* w    = (const float*)d_in[2];
    const float* bias = (const float*)d_in[3];
    float* out = (float*)d_out;

    void *px16 = nullptr, *pw2 = nullptr, *pbt = nullptr, *ppart = nullptr;
    cudaGetSymbolAddress(&px16, g_x16);
    cudaGetSymbolAddress(&pw2, g_w2);
    cudaGetSymbolAddress(&pbt, g_bt);
    cudaGetSymbolAddress(&ppart, g_part);

    prep_all_kernel<<<(unsigned)(PREP_X_BLKS + PREP_W_BLKS + PREP_BT_BLKS), 256>>>(
        x, coef, w, bias, (__half*)px16, (__half*)pw2, (float*)pbt);

    EncodeFn encode = nullptr;
    cudaDriverEntryPointQueryResult qr;
    cudaGetDriverEntryPoint("cuTensorMapEncodeTiled", (void**)&encode,
                            cudaEnableDefault, &qr);

    CUtensorMap tb{}, tx{};
    {   // B: w2 (O, K) fp16, K-major, SW128, box {64, TN}
        cuuint64_t dims[2]    = {(cuuint64_t)K_, (cuuint64_t)O_};
        cuuint64_t strides[1] = {(cuuint64_t)K_ * 2};
        cuuint32_t box[2]     = {64, TN};
        cuuint32_t es[2]      = {1, 1};
        encode(&tb, CU_TENSOR_MAP_DATA_TYPE_FLOAT16, 2, pw2, dims, strides, box, es,
               CU_TENSOR_MAP_INTERLEAVE_NONE, CU_TENSOR_MAP_SWIZZLE_128B,
               CU_TENSOR_MAP_L2_PROMOTION_L2_128B, CU_TENSOR_MAP_FLOAT_OOB_FILL_NONE);
    }
    {   // X: x16 (M, C) fp16, box {16, TM} (32B rows = TMA minimum), no swizzle
        cuuint64_t dims[2]    = {(cuuint64_t)C_, (cuuint64_t)M_};
        cuuint64_t strides[1] = {(cuuint64_t)C_ * 2};
        cuuint32_t box[2]     = {16, TM};
        cuuint32_t es[2]      = {1, 1};
        encode(&tx, CU_TENSOR_MAP_DATA_TYPE_FLOAT16, 2, px16, dims, strides, box, es,
               CU_TENSOR_MAP_INTERLEAVE_NONE, CU_TENSOR_MAP_SWIZZLE_NONE,
               CU_TENSOR_MAP_L2_PROMOTION_L2_128B, CU_TENSOR_MAP_FLOAT_OOB_FILL_NONE);
    }

    cudaFuncSetAttribute(gemm_kernel, cudaFuncAttributeMaxDynamicSharedMemorySize,
                         SMEM_TOTAL);
    gemm_kernel<<<GRID_GEMM, 288, SMEM_TOTAL>>>(tb, tx, coef, (const float*)pbt,
                                                (float*)ppart, out);

    reduce_kernel<<<(unsigned)(REDUCE_ELEMS / 256), 256>>>(
        (const float*)ppart, (const float*)pbt, out);
}